// round 17
// baseline (speedup 1.0000x reference)
#include <cuda_runtime.h>
#include <cuda_bf16.h>
#include <cstdint>
#include <math.h>

// ---------------- problem constants ----------------
#define N0   4096
#define INC  128
#define HC   512
#define OC   64
#define KP1  2000
#define KP2  1000
#define KP3  500
#define DEG  192

#define ACT_NONE 0
#define ACT_RELU 1
#define ACT_SIGM 2

// packed-weight layout
#define WLEN_D0 (384*512)
#define WSEG    (1536*512)
#define WOFF_D0 0
#define WOFF_D1 (WLEN_D0)
#define WOFF_D2 (WOFF_D1 + WSEG)
#define WOFF_D3 (WOFF_D2 + WSEG)
#define WOFF_U0 (WOFF_D3 + WSEG)
#define WOFF_U1 (WOFF_U0 + WSEG)
#define WOFF_U2 (WOFF_U1 + WSEG)
#define WLEN_U2 (1536*128)
#define WTOT (WOFF_U2 + WLEN_U2)

// ---------------- scratch ----------------
__device__ float g_Augp[(size_t)1024*1024];
__device__ float g_h0 [(size_t)N0*HC];
__device__ float g_h1 [(size_t)KP1*HC];
__device__ float g_h2 [(size_t)KP2*HC];
__device__ float g_h3 [(size_t)KP3*HC];
__device__ float g_hb [(size_t)KP1*HC];
__device__ float g_xw [(size_t)N0*HC];
__device__ float g_t  [(size_t)2048*1024];
__device__ float g_dis0[N0];
__device__ float g_dis1[2048];
__device__ float g_dis2[2048];
__device__ float g_dis3[1024];
__device__ float g_sc [N0];
__device__ int   g_perm0[KP1];
__device__ int   g_perm1[KP2];
__device__ int   g_perm2[KP3];
__device__ int   g_inv0[N0];
__device__ int   g_inv1[2048];
__device__ int   g_inv2[1024];
__device__ int   g_ccnt[N0];
__device__ int   g_ccol[(size_t)N0*DEG];
__device__ float g_cval[(size_t)N0*DEG];
__device__ unsigned char g_m0[(size_t)N0*N0];
__device__ __nv_bfloat16 g_bA1 [(size_t)2048*2048];
__device__ __nv_bfloat16 g_bX2 [(size_t)1024*2048];
__device__ __nv_bfloat16 g_bX3 [(size_t)512*1024];
__device__ __nv_bfloat16 g_G  [(size_t)1024*2048];
__device__ __nv_bfloat16 g_Q  [(size_t)512*2048];
__device__ __nv_bfloat16 g_zpk[(size_t)2048*1024];
__device__ __nv_bfloat16 g_Xpk[(size_t)4096*1536];
__device__ __nv_bfloat16 g_Wall[WTOT];

// ---------------- cp.async helpers ----------------
#define CPASYNC16(dst_u32, src_ptr) \
    asm volatile("cp.async.ca.shared.global [%0], [%1], 16;" :: "r"(dst_u32), "l"(src_ptr))
#define CP_COMMIT() asm volatile("cp.async.commit_group;")

#define NN_AS (128*40)
#define NN_BS (32*136)
#define NT_AS (128*40)
#define NT_BS (128*40)
#define NN_SMEM (4 * (NN_AS + NN_BS) * 2)
#define NT_SMEM (4 * (NT_AS + NT_BS) * 2)

// ---------------- NN GEMM ----------------
__global__ void __launch_bounds__(256) hgemm_nn(int M, int N, int K,
        const __nv_bfloat16* __restrict__ A, int lda,
        const __nv_bfloat16* __restrict__ B, int ldb,
        float* __restrict__ C, int ldc, int acc,
        const float* __restrict__ bias, int act) {
    extern __shared__ __nv_bfloat16 dsm[];
    __nv_bfloat16* Asm = dsm;
    __nv_bfloat16* Bsm = dsm + 4 * NN_AS;
    const int tid  = threadIdx.x;
    const int lane = tid & 31;
    const int warp = tid >> 5;
    const int wm = (warp >> 2) * 64;
    const int wn = (warp & 3) * 32;
    const int m0 = blockIdx.y * 128;
    const int n0 = blockIdx.x * 128;
    const int Kc = K / gridDim.z;
    const int k0 = blockIdx.z * Kc;

    const int ar = tid >> 1, ac = (tid & 1) * 16;
    const int br = tid >> 3, bc = (tid & 7) * 16;

    float c[4][4][4];
#pragma unroll
    for (int mt = 0; mt < 4; mt++)
#pragma unroll
        for (int nt = 0; nt < 4; nt++)
#pragma unroll
            for (int r = 0; r < 4; r++) c[mt][nt][r] = 0.f;

    const int ntile = Kc >> 5;

#define NN_LOAD(s, kk) { \
    unsigned da = (unsigned)__cvta_generic_to_shared(Asm + (s) * NN_AS + ar * 40 + ac); \
    const __nv_bfloat16* pa = A + (size_t)(m0 + ar) * lda + (kk) + ac; \
    CPASYNC16(da, pa); CPASYNC16(da + 16, pa + 8); \
    unsigned db = (unsigned)__cvta_generic_to_shared(Bsm + (s) * NN_BS + br * 136 + bc); \
    const __nv_bfloat16* pb = B + (size_t)((kk) + br) * ldb + n0 + bc; \
    CPASYNC16(db, pb); CPASYNC16(db + 16, pb + 8); }

    for (int p = 0; p < 3; ++p) {
        if (p < ntile) NN_LOAD(p, k0 + p * 32);
        CP_COMMIT();
    }

    for (int it = 0; it < ntile; ++it) {
        asm volatile("cp.async.wait_group 2;");
        __syncthreads();
        int pf = it + 3;
        if (pf < ntile) NN_LOAD(pf & 3, k0 + pf * 32);
        CP_COMMIT();

        const int s = it & 3;
        const __nv_bfloat16* As_s = Asm + s * NN_AS;
        const __nv_bfloat16* Bs_s = Bsm + s * NN_BS;
#pragma unroll
        for (int ks = 0; ks < 32; ks += 16) {
            uint32_t af[4][4];
#pragma unroll
            for (int mt = 0; mt < 4; mt++) {
                unsigned addr = (unsigned)__cvta_generic_to_shared(
                    As_s + (wm + mt * 16 + (lane & 15)) * 40 + ks + (lane >> 4) * 8);
                asm volatile("ldmatrix.sync.aligned.m8n8.x4.shared.b16 {%0,%1,%2,%3}, [%4];"
                    : "=r"(af[mt][0]), "=r"(af[mt][1]), "=r"(af[mt][2]), "=r"(af[mt][3])
                    : "r"(addr));
            }
            uint32_t bfr[4][2];
#pragma unroll
            for (int nt = 0; nt < 4; nt++) {
                unsigned addr = (unsigned)__cvta_generic_to_shared(
                    Bs_s + (ks + (lane & 15)) * 136 + wn + nt * 8);
                asm volatile("ldmatrix.sync.aligned.m8n8.x2.trans.shared.b16 {%0,%1}, [%2];"
                    : "=r"(bfr[nt][0]), "=r"(bfr[nt][1]) : "r"(addr));
            }
#pragma unroll
            for (int mt = 0; mt < 4; mt++)
#pragma unroll
                for (int nt = 0; nt < 4; nt++)
                    asm volatile(
                        "mma.sync.aligned.m16n8k16.row.col.f32.bf16.bf16.f32 "
                        "{%0,%1,%2,%3}, {%4,%5,%6,%7}, {%8,%9}, {%0,%1,%2,%3};"
                        : "+f"(c[mt][nt][0]), "+f"(c[mt][nt][1]),
                          "+f"(c[mt][nt][2]), "+f"(c[mt][nt][3])
                        : "r"(af[mt][0]), "r"(af[mt][1]), "r"(af[mt][2]), "r"(af[mt][3]),
                          "r"(bfr[nt][0]), "r"(bfr[nt][1]));
        }
        __syncthreads();
    }

    const int r0 = lane >> 2, c0 = (lane & 3) * 2;
#pragma unroll
    for (int mt = 0; mt < 4; mt++)
#pragma unroll
        for (int nt = 0; nt < 4; nt++) {
            int row = m0 + wm + mt * 16 + r0;
            int col = n0 + wn + nt * 8 + c0;
            float* p0 = C + (size_t)row * ldc + col;
            float* p1 = C + (size_t)(row + 8) * ldc + col;
            if (acc == 2) {
                atomicAdd(p0,     c[mt][nt][0]); atomicAdd(p0 + 1, c[mt][nt][1]);
                atomicAdd(p1,     c[mt][nt][2]); atomicAdd(p1 + 1, c[mt][nt][3]);
            } else {
                float v0 = c[mt][nt][0], v1 = c[mt][nt][1];
                float v2 = c[mt][nt][2], v3 = c[mt][nt][3];
                if (bias) { v0 += bias[col]; v1 += bias[col + 1];
                            v2 += bias[col]; v3 += bias[col + 1]; }
                if (act == ACT_RELU) {
                    v0 = fmaxf(v0, 0.f); v1 = fmaxf(v1, 0.f);
                    v2 = fmaxf(v2, 0.f); v3 = fmaxf(v3, 0.f);
                }
                p0[0] = v0; p0[1] = v1;
                p1[0] = v2; p1[1] = v3;
            }
        }
}

// ---------------- NT GEMM (tri-symmetric option) ----------------
__global__ void __launch_bounds__(256) hgemm_nt(int M, int N, int K,
        const __nv_bfloat16* __restrict__ A, int lda,
        const __nv_bfloat16* __restrict__ B, int ldb,
        float* __restrict__ C, int ldc, int acc, int tri) {
    extern __shared__ __nv_bfloat16 dsm[];
    __nv_bfloat16* Asm = dsm;
    __nv_bfloat16* Bsm = dsm + 4 * NT_AS;
    const int tid  = threadIdx.x;
    const int lane = tid & 31;
    const int warp = tid >> 5;
    const int wm = (warp >> 2) * 64;
    const int wn = (warp & 3) * 32;

    int m0, n0;
    if (tri) {
        int bid = blockIdx.x;
        int by = (int)((sqrtf(8.f * bid + 1.f) - 1.f) * 0.5f);
        while ((by + 1) * (by + 2) / 2 <= bid) by++;
        while (by * (by + 1) / 2 > bid) by--;
        int bx = bid - by * (by + 1) / 2;
        m0 = bx * 128;
        n0 = by * 128;
    } else {
        m0 = blockIdx.y * 128;
        n0 = blockIdx.x * 128;
    }
    const int Kc = K / gridDim.z;
    const int k0 = blockIdx.z * Kc;

    const int ar = tid >> 1, ac = (tid & 1) * 16;

    float c[4][4][4];
#pragma unroll
    for (int mt = 0; mt < 4; mt++)
#pragma unroll
        for (int nt = 0; nt < 4; nt++)
#pragma unroll
            for (int r = 0; r < 4; r++) c[mt][nt][r] = 0.f;

    const int ntile = Kc >> 5;

#define NT_LOAD(s, kk) { \
    unsigned da = (unsigned)__cvta_generic_to_shared(Asm + (s) * NT_AS + ar * 40 + ac); \
    const __nv_bfloat16* pa = A + (size_t)(m0 + ar) * lda + (kk) + ac; \
    CPASYNC16(da, pa); CPASYNC16(da + 16, pa + 8); \
    unsigned db = (unsigned)__cvta_generic_to_shared(Bsm + (s) * NT_BS + ar * 40 + ac); \
    const __nv_bfloat16* pb = B + (size_t)(n0 + ar) * ldb + (kk) + ac; \
    CPASYNC16(db, pb); CPASYNC16(db + 16, pb + 8); }

    for (int p = 0; p < 3; ++p) {
        if (p < ntile) NT_LOAD(p, k0 + p * 32);
        CP_COMMIT();
    }

    for (int it = 0; it < ntile; ++it) {
        asm volatile("cp.async.wait_group 2;");
        __syncthreads();
        int pf = it + 3;
        if (pf < ntile) NT_LOAD(pf & 3, k0 + pf * 32);
        CP_COMMIT();

        const int s = it & 3;
        const __nv_bfloat16* As_s = Asm + s * NT_AS;
        const __nv_bfloat16* Bs_s = Bsm + s * NT_BS;
#pragma unroll
        for (int ks = 0; ks < 32; ks += 16) {
            uint32_t af[4][4];
#pragma unroll
            for (int mt = 0; mt < 4; mt++) {
                unsigned addr = (unsigned)__cvta_generic_to_shared(
                    As_s + (wm + mt * 16 + (lane & 15)) * 40 + ks + (lane >> 4) * 8);
                asm volatile("ldmatrix.sync.aligned.m8n8.x4.shared.b16 {%0,%1,%2,%3}, [%4];"
                    : "=r"(af[mt][0]), "=r"(af[mt][1]), "=r"(af[mt][2]), "=r"(af[mt][3])
                    : "r"(addr));
            }
            uint32_t bfr[4][2];
#pragma unroll
            for (int nt = 0; nt < 4; nt++) {
                unsigned addr = (unsigned)__cvta_generic_to_shared(
                    Bs_s + (wn + nt * 8 + (lane & 7)) * 40 + ks + ((lane >> 3) & 1) * 8);
                asm volatile("ldmatrix.sync.aligned.m8n8.x2.shared.b16 {%0,%1}, [%2];"
                    : "=r"(bfr[nt][0]), "=r"(bfr[nt][1]) : "r"(addr));
            }
#pragma unroll
            for (int mt = 0; mt < 4; mt++)
#pragma unroll
                for (int nt = 0; nt < 4; nt++)
                    asm volatile(
                        "mma.sync.aligned.m16n8k16.row.col.f32.bf16.bf16.f32 "
                        "{%0,%1,%2,%3}, {%4,%5,%6,%7}, {%8,%9}, {%0,%1,%2,%3};"
                        : "+f"(c[mt][nt][0]), "+f"(c[mt][nt][1]),
                          "+f"(c[mt][nt][2]), "+f"(c[mt][nt][3])
                        : "r"(af[mt][0]), "r"(af[mt][1]), "r"(af[mt][2]), "r"(af[mt][3]),
                          "r"(bfr[nt][0]), "r"(bfr[nt][1]));
        }
        __syncthreads();
    }

    const int r0 = lane >> 2, c0 = (lane & 3) * 2;
#pragma unroll
    for (int mt = 0; mt < 4; mt++)
#pragma unroll
        for (int nt = 0; nt < 4; nt++) {
            int row = m0 + wm + mt * 16 + r0;
            int col = n0 + wn + nt * 8 + c0;
            float* p0 = C + (size_t)row * ldc + col;
            float* p1 = C + (size_t)(row + 8) * ldc + col;
            if (acc == 2) {
                atomicAdd(p0,     c[mt][nt][0]); atomicAdd(p0 + 1, c[mt][nt][1]);
                atomicAdd(p1,     c[mt][nt][2]); atomicAdd(p1 + 1, c[mt][nt][3]);
            } else {
                p0[0] = c[mt][nt][0]; p0[1] = c[mt][nt][1];
                p1[0] = c[mt][nt][2]; p1[1] = c[mt][nt][3];
            }
        }
}

// ---------------- graph / elementwise kernels ----------------
__global__ void k_edges_m(const int* __restrict__ ei, int E, unsigned char* __restrict__ M) {
    int e = blockIdx.x * blockDim.x + threadIdx.x;
    if (e >= E) return;
    int s = ei[e], d = ei[E + e];
    M[(size_t)s * N0 + d] = 1;
    M[(size_t)d * N0 + s] = 1;
}

__global__ void k_csr_m(const unsigned char* __restrict__ M, int n,
                        int* __restrict__ cnt, int* __restrict__ col,
                        float* __restrict__ val, float* __restrict__ dis) {
    __shared__ int c;
    __shared__ float red[256];
    int row = blockIdx.x;
    if (threadIdx.x == 0) c = 0;
    __syncthreads();
    const unsigned char* Mr = M + (size_t)row * n;
    float lsum = 0.f;
    for (int j = threadIdx.x; j < n; j += 256) {
        float v = (float)Mr[j] + ((j == row) ? 1.f : 0.f);
        if (v != 0.f) {
            int s = atomicAdd(&c, 1);
            col[(size_t)row * DEG + s] = j;
            val[(size_t)row * DEG + s] = v;
            lsum += v;
        }
    }
    red[threadIdx.x] = lsum;
    __syncthreads();
    for (int o = 128; o > 0; o >>= 1) {
        if (threadIdx.x < o) red[threadIdx.x] += red[threadIdx.x + o];
        __syncthreads();
    }
    if (threadIdx.x == 0) { cnt[row] = c; dis[row] = rsqrtf(red[0]); }
}

// fused SpMM + 3x pack: Xp[r] = [hi|lo|hi] of D(A+I)D x  (level-0 down)
__global__ void k_spmm_pack(const int* __restrict__ cnt, const int* __restrict__ col,
                            const float* __restrict__ val,
                            const float* __restrict__ X, int C,
                            const float* __restrict__ dis,
                            __nv_bfloat16* __restrict__ Xp) {
    int row = blockIdx.x, c = threadIdx.x;
    if (c >= C) return;
    int m = cnt[row];
    const int* cr = col + (size_t)row * DEG;
    const float* vr = val + (size_t)row * DEG;
    float a0 = 0.f, a1 = 0.f, a2 = 0.f, a3 = 0.f;
    int e = 0;
    for (; e + 3 < m; e += 4) {
        int j0 = cr[e], j1 = cr[e + 1], j2 = cr[e + 2], j3 = cr[e + 3];
        float w0 = vr[e] * dis[j0], w1 = vr[e + 1] * dis[j1];
        float w2 = vr[e + 2] * dis[j2], w3 = vr[e + 3] * dis[j3];
        a0 += w0 * X[(size_t)j0 * C + c];
        a1 += w1 * X[(size_t)j1 * C + c];
        a2 += w2 * X[(size_t)j2 * C + c];
        a3 += w3 * X[(size_t)j3 * C + c];
    }
    for (; e < m; e++) {
        int j = cr[e];
        a0 += vr[e] * dis[j] * X[(size_t)j * C + c];
    }
    float v = ((a0 + a1) + (a2 + a3)) * dis[row];
    __nv_bfloat16 hi = __float2bfloat16(v);
    __nv_bfloat16 lo = __float2bfloat16(v - __bfloat162float(hi));
    __nv_bfloat16* out = Xp + (size_t)row * (3 * C) + c;
    out[0]     = hi;
    out[C]     = lo;
    out[2 * C] = hi;
}

// SpMM GCN (final layer), 4-way unrolled
__global__ void k_spmm(const int* __restrict__ cnt, const int* __restrict__ col,
                       const float* __restrict__ val,
                       const float* __restrict__ X, int C, int ldx,
                       const float* __restrict__ dis,
                       const float* __restrict__ bias, int act,
                       float* __restrict__ S) {
    int row = blockIdx.x, c = threadIdx.x;
    if (c >= C) return;
    int m = cnt[row];
    const int* cr = col + (size_t)row * DEG;
    const float* vr = val + (size_t)row * DEG;
    float a0 = 0.f, a1 = 0.f, a2 = 0.f, a3 = 0.f;
    int e = 0;
    for (; e + 3 < m; e += 4) {
        int j0 = cr[e], j1 = cr[e + 1], j2 = cr[e + 2], j3 = cr[e + 3];
        float w0 = vr[e] * dis[j0], w1 = vr[e + 1] * dis[j1];
        float w2 = vr[e + 2] * dis[j2], w3 = vr[e + 3] * dis[j3];
        a0 += w0 * X[(size_t)j0 * ldx + c];
        a1 += w1 * X[(size_t)j1 * ldx + c];
        a2 += w2 * X[(size_t)j2 * ldx + c];
        a3 += w3 * X[(size_t)j3 * ldx + c];
    }
    for (; e < m; e++) {
        int j = cr[e];
        a0 += vr[e] * dis[j] * X[(size_t)j * ldx + c];
    }
    float v = ((a0 + a1) + (a2 + a3)) * dis[row];
    if (bias) v += bias[c];
    if (act == ACT_SIGM) v = 1.f / (1.f + expf(-v));
    S[(size_t)row * C + c] = v;
}

// SpGEMM pool0 (warp-parallel) with fused dis output
__global__ void __launch_bounds__(256) k_spgemm(
        const int* __restrict__ cnt, const int* __restrict__ col,
        const float* __restrict__ val, const int* __restrict__ perm,
        const int* __restrict__ inv, int k, int np,
        __nv_bfloat16* __restrict__ bA1, float* __restrict__ disO) {
    __shared__ float acc[2048];
    __shared__ float red[256];
    int r = blockIdx.x;
    for (int i = threadIdx.x; i < np; i += 256) acc[i] = 0.f;
    __syncthreads();
    if (r < k) {
        int row = perm[r];
        int m = cnt[row];
        const int* cr = col + (size_t)row * DEG;
        const float* vr = val + (size_t)row * DEG;
        int warp = threadIdx.x >> 5, lane = threadIdx.x & 31;
        for (int e1 = warp; e1 < m; e1 += 8) {
            int j = cr[e1];
            float w1 = vr[e1];
            int mj = cnt[j];
            const int* cj = col + (size_t)j * DEG;
            const float* vj = val + (size_t)j * DEG;
            for (int e2 = lane; e2 < mj; e2 += 32) {
                int cidx = inv[cj[e2]];
                if (cidx >= 0) atomicAdd(&acc[cidx], w1 * vj[e2]);
            }
        }
    }
    __syncthreads();
    __nv_bfloat16* out = bA1 + (size_t)r * np;
    float lsum = 0.f;
    for (int cidx = threadIdx.x; cidx < np; cidx += 256) {
        float v = (r < k) ? ((cidx == r) ? 1.f : acc[cidx]) : 0.f;
        out[cidx] = __float2bfloat16(v);
        lsum += v;
    }
    red[threadIdx.x] = lsum;
    __syncthreads();
    for (int o = 128; o > 0; o >>= 1) {
        if (threadIdx.x < o) red[threadIdx.x] += red[threadIdx.x + o];
        __syncthreads();
    }
    if (threadIdx.x == 0 && r < k) disO[r] = rsqrtf(red[0]);
}

// scale+pack, single read 2 writes: zpk (np x 2Cpad) = [hi | lo]
__global__ void k_scale_pack(const float* __restrict__ xw, const float* __restrict__ dis,
                             int n, int np, int C, int Cpad,
                             __nv_bfloat16* __restrict__ zpk) {
    int i = blockIdx.x * blockDim.x + threadIdx.x;
    if (i >= np * Cpad) return;
    int r = i / Cpad, cc = i - r * Cpad;
    float v = (r < n && cc < C) ? dis[r] * xw[(size_t)r * C + cc] : 0.f;
    __nv_bfloat16 hi = __float2bfloat16(v);
    __nv_bfloat16 lo = __float2bfloat16(v - __bfloat162float(hi));
    __nv_bfloat16* out = zpk + (size_t)r * (2 * Cpad) + cc;
    out[0]    = hi;
    out[Cpad] = lo;
}

// stacked scale+pack, single read 4 writes
__global__ void k_scale_pack_stk(const float* __restrict__ xw, const float* __restrict__ dis,
                                 int n, int np, int C,
                                 __nv_bfloat16* __restrict__ Bp) {
    int i = blockIdx.x * blockDim.x + threadIdx.x;
    if (i >= np * C) return;
    int r = i / C, cc = i - r * C;
    float v = (r < n) ? dis[r] * xw[(size_t)r * C + cc] : 0.f;
    __nv_bfloat16 hi = __float2bfloat16(v);
    __nv_bfloat16 lo = __float2bfloat16(v - __bfloat162float(hi));
    int W = 2 * C;
    __nv_bfloat16* top = Bp + (size_t)r * W + cc;
    __nv_bfloat16* bot = Bp + (size_t)(np + r) * W + cc;
    top[0] = hi; top[C] = lo;
    bot[0] = lo; bot[C] = hi;
}

// fused pool gather + pack, single read 3 writes
__global__ void k_pool_pack(const float* __restrict__ h, int C,
                            const int* __restrict__ perm, const float* __restrict__ score,
                            int k, int kpad, __nv_bfloat16* __restrict__ Xp) {
    int i = blockIdx.x * blockDim.x + threadIdx.x;
    if (i >= kpad * C) return;
    int r = i / C, cc = i - r * C;
    float v = 0.f;
    if (r < k) {
        int pr = perm[r];
        v = h[(size_t)pr * C + cc] * score[pr];
    }
    __nv_bfloat16 hi = __float2bfloat16(v);
    __nv_bfloat16 lo = __float2bfloat16(v - __bfloat162float(hi));
    __nv_bfloat16* out = Xp + (size_t)r * (3 * C) + cc;
    out[0]     = hi;
    out[C]     = lo;
    out[2 * C] = hi;
}

// fused unpool + pack, single read 3 writes
__global__ void k_unpool_pack(const float* __restrict__ res, const float* __restrict__ hs,
                              const int* __restrict__ inv, int n, int np, int C,
                              __nv_bfloat16* __restrict__ Xp) {
    int i = blockIdx.x * blockDim.x + threadIdx.x;
    if (i >= np * C) return;
    int r = i / C, cc = i - r * C;
    float v = 0.f;
    if (r < n) {
        v = res[(size_t)r * C + cc];
        int s = inv[r];
        if (s >= 0) v += hs[(size_t)s * C + cc];
    }
    __nv_bfloat16 hi = __float2bfloat16(v);
    __nv_bfloat16 lo = __float2bfloat16(v - __bfloat162float(hi));
    __nv_bfloat16* out = Xp + (size_t)r * (3 * C) + cc;
    out[0]     = hi;
    out[C]     = lo;
    out[2 * C] = hi;
}

__device__ __forceinline__ __nv_bfloat16 packw_elem(const float* W, int K, int N, int Npad, int idx) {
    int r = idx / Npad, cc = idx - r * Npad;
    int rr = r; if (rr >= K) rr -= K; if (rr >= K) rr -= K;
    float v = (cc < N) ? W[(size_t)rr * N + cc] : 0.f;
    __nv_bfloat16 hi = __float2bfloat16(v);
    return (r < 2 * K) ? hi : __float2bfloat16(v - __bfloat162float(hi));
}

__global__ void k_packW_all(const float* __restrict__ Wd0, const float* __restrict__ Wd1,
                            const float* __restrict__ Wd2, const float* __restrict__ Wd3,
                            const float* __restrict__ Wu0, const float* __restrict__ Wu1,
                            const float* __restrict__ Wu2, __nv_bfloat16* __restrict__ out) {
    int i = blockIdx.x * blockDim.x + threadIdx.x;
    if (i >= WTOT) return;
    if (i < WOFF_D1)      out[i] = packw_elem(Wd0, 128, 512, 512, i - WOFF_D0);
    else if (i < WOFF_D2) out[i] = packw_elem(Wd1, 512, 512, 512, i - WOFF_D1);
    else if (i < WOFF_D3) out[i] = packw_elem(Wd2, 512, 512, 512, i - WOFF_D2);
    else if (i < WOFF_U0) out[i] = packw_elem(Wd3, 512, 512, 512, i - WOFF_D3);
    else if (i < WOFF_U1) out[i] = packw_elem(Wu0, 512, 512, 512, i - WOFF_U0);
    else if (i < WOFF_U2) out[i] = packw_elem(Wu1, 512, 512, 512, i - WOFF_U1);
    else                  out[i] = packw_elem(Wu2, 512, 64, 128, i - WOFF_U2);
}

__global__ void k_epilogue_sum2(const float* __restrict__ t, int ldt, int half,
                                const float* __restrict__ dis, const float* __restrict__ b,
                                int n, int C, float* __restrict__ out, int act) {
    int i = blockIdx.x * blockDim.x + threadIdx.x;
    if (i >= n * C) return;
    int r = i / C, cc = i - r * C;
    float v = dis[r] * (t[(size_t)r * ldt + cc] + t[(size_t)r * ldt + cc + half]) + b[cc];
    if (act == ACT_RELU) v = fmaxf(v, 0.f);
    else if (act == ACT_SIGM) v = 1.f / (1.f + expf(-v));
    out[i] = v;
}

// crop + pack + dis, block per row (upper-stored symmetric Augp + I)
__global__ void __launch_bounds__(256) k_crop_pack_X(
        const float* __restrict__ Augp, int kpad, int k, int np,
        __nv_bfloat16* __restrict__ X, float* __restrict__ disO) {
    __shared__ float red[256];
    int r = blockIdx.x;
    float lsum = 0.f;
    __nv_bfloat16* Xr = X + (size_t)r * (2 * np);
    for (int cc = threadIdx.x; cc < np; cc += 256) {
        float v = 0.f;
        if (r < k && cc < k) {
            if (r == cc) v = 1.f;
            else {
                int rr = (r < cc) ? r : cc;
                int c2 = (r < cc) ? cc : r;
                v = Augp[(size_t)rr * kpad + c2];
            }
        }
        __nv_bfloat16 hi = __float2bfloat16(v);
        Xr[cc]      = hi;
        Xr[np + cc] = __float2bfloat16(v - __bfloat162float(hi));
        lsum += v;
    }
    red[threadIdx.x] = lsum;
    __syncthreads();
    for (int o = 128; o > 0; o >>= 1) {
        if (threadIdx.x < o) red[threadIdx.x] += red[threadIdx.x + o];
        __syncthreads();
    }
    if (threadIdx.x == 0 && r < k) disO[r] = rsqrtf(red[0]);
}

__global__ void k_gather_rows(const __nv_bfloat16* __restrict__ bApI, int np,
                              const int* __restrict__ perm, int k, int kpad,
                              __nv_bfloat16* __restrict__ G) {
    int i = blockIdx.x * blockDim.x + threadIdx.x;
    if (i >= kpad * np) return;
    int r = i / np, j = i - r * np;
    G[i] = (r < k) ? bApI[(size_t)perm[r] * np + j] : __float2bfloat16(0.f);
}

__global__ void k_gather_PQ_b(const __nv_bfloat16* __restrict__ X2, int np,
                              const int* __restrict__ perm, int k, int kpad,
                              __nv_bfloat16* __restrict__ P,
                              __nv_bfloat16* __restrict__ Q) {
    int i = blockIdx.x * blockDim.x + threadIdx.x;
    int W = 2 * np;
    if (i >= kpad * W) return;
    int r = i / W, j = i - r * W;
    __nv_bfloat16 v = (r < k) ? X2[(size_t)perm[r] * W + j] : __float2bfloat16(0.f);
    P[i] = v;
    int js = (j < np) ? j + np : j - np;
    Q[(size_t)r * W + js] = v;
}

// scores with inline p-norm
__global__ void k_scores(const float* __restrict__ h, int n, int C,
                         const float* __restrict__ p,
                         float* __restrict__ score) {
    __shared__ float s_pn;
    int tid = threadIdx.x;
    if (tid < 32) {
        float s = 0.f;
        for (int i = tid; i < C; i += 32) s += p[i] * p[i];
        for (int o = 16; o > 0; o >>= 1) s += __shfl_xor_sync(0xffffffffu, s, o);
        if (tid == 0) s_pn = sqrtf(s);
    }
    __syncthreads();
    int row = blockIdx.x * 8 + (tid >> 5);
    int lane = tid & 31;
    if (row >= n) return;
    const float* hr = h + (size_t)row * C;
    float s = 0.f;
    for (int cc = lane; cc < C; cc += 32) s += hr[cc] * p[cc];
    for (int o = 16; o > 0; o >>= 1) s += __shfl_xor_sync(0xffffffffu, s, o);
    if (lane == 0) score[row] = tanhf(s / s_pn);
}

// top-k select with fused inv construction
__global__ void __launch_bounds__(1024) k_topk_sel(const float* __restrict__ score,
                                                   int n, int k, int* __restrict__ perm,
                                                   int* __restrict__ inv) {
    __shared__ float sc[4096];
    __shared__ int cnt;
    int tid = threadIdx.x;
    for (int i = tid; i < n; i += 1024) { sc[i] = score[i]; inv[i] = -1; }
    __syncthreads();
    float lo = -1.1f, hi = 1.1f;
    for (int it = 0; it < 40; ++it) {
        float mid = 0.5f * (lo + hi);
        if (tid == 0) cnt = 0;
        __syncthreads();
        int c = 0;
        for (int i = tid; i < n; i += 1024) if (sc[i] > mid) c++;
        for (int o = 16; o > 0; o >>= 1) c += __shfl_xor_sync(0xffffffffu, c, o);
        if ((tid & 31) == 0 && c) atomicAdd(&cnt, c);
        __syncthreads();
        if (cnt >= k) lo = mid; else hi = mid;
        __syncthreads();
    }
    if (tid == 0) cnt = 0;
    __syncthreads();
    for (int i = tid; i < n; i += 1024)
        if (sc[i] > hi) { int s = atomicAdd(&cnt, 1); perm[s] = i; inv[i] = s; }
    __syncthreads();
    for (int i = tid; i < n; i += 1024)
        if (sc[i] > lo && sc[i] <= hi) {
            int s = atomicAdd(&cnt, 1);
            if (s < k) { perm[s] = i; inv[i] = s; }
        }
}

// ---------------- host orchestration ----------------
static void run_nn(int M, int N, int K, const __nv_bfloat16* A, int lda,
                   const __nv_bfloat16* B, int ldb, float* C, int ldc, int acc, int splitk,
                   const float* bias, int act) {
    cudaFuncSetAttribute(hgemm_nn, cudaFuncAttributeMaxDynamicSharedMemorySize, NN_SMEM);
    dim3 g(N / 128, M / 128, splitk);
    hgemm_nn<<<g, 256, NN_SMEM>>>(M, N, K, A, lda, B, ldb, C, ldc, acc, bias, act);
}
static void run_nt_tri(int M, int K, const __nv_bfloat16* A, int lda,
                       const __nv_bfloat16* B, int ldb, float* C, int ldc, int splitk) {
    cudaFuncSetAttribute(hgemm_nt, cudaFuncAttributeMaxDynamicSharedMemorySize, NT_SMEM);
    int T = M / 128;
    dim3 g(T * (T + 1) / 2, 1, splitk);
    hgemm_nt<<<g, 256, NT_SMEM>>>(M, M, K, A, lda, B, ldb, C, ldc, 2, 1);
}

static void run_xw_pre(const __nv_bfloat16* Xp, int np, int K3,
                       const __nv_bfloat16* Wp, int N,
                       const float* bias, int act, float* out, int splitk) {
    if (splitk > 1) {
        cudaMemsetAsync(out, 0, (size_t)np * N * sizeof(float), 0);
        run_nn(np, N, K3, Xp, K3, Wp, N, out, N, 2, splitk, nullptr, ACT_NONE);
    } else {
        run_nn(np, N, K3, Xp, K3, Wp, N, out, N, 0, 1, bias, act);
    }
}

static void run_gcn_exact(const __nv_bfloat16* bApI, int n, int np,
                          const __nv_bfloat16* Xp, int K3,
                          const __nv_bfloat16* Wp, int outC, const float* b,
                          float* out, int act, int xwsplit, int adjsplit,
                          float* xw, float* t, const float* dis, __nv_bfloat16* zpk) {
    run_xw_pre(Xp, np, K3, Wp, outC, nullptr, ACT_NONE, xw, xwsplit);
    int Cpad = outC;
    int W2 = 2 * Cpad;
    int tot = np * Cpad;
    k_scale_pack<<<(tot + 255) / 256, 256>>>(xw, dis, n, np, outC, Cpad, zpk);
    cudaMemsetAsync(t, 0, (size_t)np * W2 * sizeof(float), 0);
    run_nn(np, W2, np, bApI, np, zpk, W2, t, W2, 2, adjsplit, nullptr, ACT_NONE);
    int nc = n * outC;
    k_epilogue_sum2<<<(nc + 255) / 256, 256>>>(t, W2, Cpad, dis, b, n, outC, out, act);
}

static void run_gcn_split(const __nv_bfloat16* X2, int n, int np,
                          const __nv_bfloat16* Xp, int K3,
                          const __nv_bfloat16* Wp, int outC, const float* b,
                          float* out, int act, int xwsplit, int adjsplit,
                          float* xw, float* t, const float* dis, __nv_bfloat16* Bp) {
    run_xw_pre(Xp, np, K3, Wp, outC, nullptr, ACT_NONE, xw, xwsplit);
    int W2 = 2 * outC;
    int tot = np * outC;
    k_scale_pack_stk<<<(tot + 255) / 256, 256>>>(xw, dis, n, np, outC, Bp);
    cudaMemsetAsync(t, 0, (size_t)np * W2 * sizeof(float), 0);
    run_nn(np, W2, 2 * np, X2, 2 * np, Bp, W2, t, W2, 2, adjsplit, nullptr, ACT_NONE);
    int nc = n * outC;
    k_epilogue_sum2<<<(nc + 255) / 256, 256>>>(t, W2, outC, dis, b, n, outC, out, act);
}

static void run_scores_topk(const float* h, int n, const float* p, int k,
                            int* perm, int* inv, float* score) {
    k_scores<<<(n + 7) / 8, 256>>>(h, n, HC, p, score);
    k_topk_sel<<<1, 1024>>>(score, n, k, perm, inv);
}

extern "C" void kernel_launch(void* const* d_in, const int* in_sizes, int n_in,
                              void* d_out, int out_size) {
    const float* x   = (const float*)d_in[0];
    const int*   ei  = (const int*)  d_in[1];
    const float* Wd0 = (const float*)d_in[2];  const float* bd0 = (const float*)d_in[3];
    const float* Wd1 = (const float*)d_in[4];  const float* bd1 = (const float*)d_in[5];
    const float* Wd2 = (const float*)d_in[6];  const float* bd2 = (const float*)d_in[7];
    const float* Wd3 = (const float*)d_in[8];  const float* bd3 = (const float*)d_in[9];
    const float* p1  = (const float*)d_in[10];
    const float* p2  = (const float*)d_in[11];
    const float* p3  = (const float*)d_in[12];
    const float* Wu0 = (const float*)d_in[13]; const float* bu0 = (const float*)d_in[14];
    const float* Wu1 = (const float*)d_in[15]; const float* bu1 = (const float*)d_in[16];
    const float* Wu2 = (const float*)d_in[17]; const float* bu2 = (const float*)d_in[18];
    const int E = in_sizes[1] / 2;

    float *Augp, *h0, *h1, *h2, *h3, *hb, *xw, *t, *sc;
    float *dis0, *dis1, *dis2, *dis3;
    int *pm0, *pm1, *pm2, *inv0, *inv1, *inv2, *ccnt, *ccol;
    float *cval;
    unsigned char* m0;
    __nv_bfloat16 *bA1, *bX2, *bX3, *G, *Q, *zpk, *Xp, *Wall;
    cudaGetSymbolAddress((void**)&Augp, g_Augp);
    cudaGetSymbolAddress((void**)&h0,  g_h0);
    cudaGetSymbolAddress((void**)&h1,  g_h1);
    cudaGetSymbolAddress((void**)&h2,  g_h2);
    cudaGetSymbolAddress((void**)&h3,  g_h3);
    cudaGetSymbolAddress((void**)&hb,  g_hb);
    cudaGetSymbolAddress((void**)&xw,  g_xw);
    cudaGetSymbolAddress((void**)&t,   g_t);
    cudaGetSymbolAddress((void**)&dis0, g_dis0);
    cudaGetSymbolAddress((void**)&dis1, g_dis1);
    cudaGetSymbolAddress((void**)&dis2, g_dis2);
    cudaGetSymbolAddress((void**)&dis3, g_dis3);
    cudaGetSymbolAddress((void**)&sc,  g_sc);
    cudaGetSymbolAddress((void**)&pm0, g_perm0);
    cudaGetSymbolAddress((void**)&pm1, g_perm1);
    cudaGetSymbolAddress((void**)&pm2, g_perm2);
    cudaGetSymbolAddress((void**)&inv0, g_inv0);
    cudaGetSymbolAddress((void**)&inv1, g_inv1);
    cudaGetSymbolAddress((void**)&inv2, g_inv2);
    cudaGetSymbolAddress((void**)&ccnt, g_ccnt);
    cudaGetSymbolAddress((void**)&ccol, g_ccol);
    cudaGetSymbolAddress((void**)&cval, g_cval);
    cudaGetSymbolAddress((void**)&m0,  g_m0);
    cudaGetSymbolAddress((void**)&bA1, g_bA1);
    cudaGetSymbolAddress((void**)&bX2, g_bX2);
    cudaGetSymbolAddress((void**)&bX3, g_bX3);
    cudaGetSymbolAddress((void**)&G,   g_G);
    cudaGetSymbolAddress((void**)&Q,   g_Q);
    cudaGetSymbolAddress((void**)&zpk, g_zpk);
    cudaGetSymbolAddress((void**)&Xp,  g_Xpk);
    cudaGetSymbolAddress((void**)&Wall, g_Wall);

    // ---- upfront: pack all weights; adjacency mask -> CSR + dis0 ----
    k_packW_all<<<(WTOT + 255) / 256, 256>>>(Wd0, Wd1, Wd2, Wd3, Wu0, Wu1, Wu2, Wall);
    cudaMemsetAsync(m0, 0, (size_t)N0 * N0, 0);
    k_edges_m<<<(E + 255) / 256, 256>>>(ei, E, m0);
    k_csr_m<<<N0, 256>>>(m0, N0, ccnt, ccol, cval, dis0);

    // ---- down level 0 (sparse, exact fp32; fused spmm+pack) ----
    k_spmm_pack<<<N0, INC>>>(ccnt, ccol, cval, x, INC, dis0, Xp);
    run_xw_pre(Xp, N0, 384, Wall + WOFF_D0, HC, bd0, ACT_RELU, h0, 1);

    // pool0: bA1 + dis1 via SpGEMM (fused)
    run_scores_topk(h0, N0, p1, KP1, pm0, inv0, sc);
    k_spgemm<<<2048, 256>>>(ccnt, ccol, cval, pm0, inv0, KP1, 2048, bA1, dis1);
    k_pool_pack<<<(2048 * 512 + 255) / 256, 256>>>(h0, HC, pm0, sc, KP1, 2048, Xp);
    run_gcn_exact(bA1, KP1, 2048, Xp, 1536, Wall + WOFF_D1, HC, bd1, h1, ACT_RELU, 4, 2,
                  xw, t, dis1, zpk);

    // pool1: A2 submatrix via G@G^T; crop+pack+dis fused
    run_scores_topk(h1, KP1, p2, KP2, pm1, inv1, sc);
    k_gather_rows<<<(1024 * 2048 + 255) / 256, 256>>>(bA1, 2048, pm1, KP2, 1024, G);
    cudaMemsetAsync(Augp, 0, (size_t)1024 * 1024 * sizeof(float), 0);
    run_nt_tri(1024, 2048, G, 2048, G, 2048, Augp, 1024, 8);
    k_pool_pack<<<(1024 * 512 + 255) / 256, 256>>>(h1, HC, pm1, sc, KP2, 1024, Xp);
    k_crop_pack_X<<<1024, 256>>>(Augp, 1024, KP2, 1024, bX2, dis2);
    run_gcn_split(bX2, KP2, 1024, Xp, 1536, Wall + WOFF_D2, HC, bd2, h2, ACT_RELU, 8, 4,
                  xw, t, dis2, zpk);

    // pool2: A3 = P@P^T + P@Q^T; crop+pack+dis fused
    run_scores_topk(h2, KP2, p3, KP3, pm2, inv2, sc);
    k_gather_PQ_b<<<(512 * 2048 + 255) / 256, 256>>>(bX2, 1024, pm2, KP3, 512, G, Q);
    cudaMemsetAsync(Augp, 0, (size_t)512 * 512 * sizeof(float), 0);
    run_nt_tri(512, 2048, G, 2048, G, 2048, Augp, 512, 8);
    run_nt_tri(512, 2048, G, 2048, Q, 2048, Augp, 512, 8);
    k_pool_pack<<<(512 * 512 + 255) / 256, 256>>>(h2, HC, pm2, sc, KP3, 512, Xp);
    k_crop_pack_X<<<512, 256>>>(Augp, 512, KP3, 512, bX3, dis3);
    run_gcn_split(bX3, KP3, 512, Xp, 1536, Wall + WOFF_D3, HC, bd3, h3, ACT_RELU, 8, 8,
                  xw, t, dis3, zpk);

    // ---- up path (fused unpool + pack) ----
    k_unpool_pack<<<(1024 * 512 + 255) / 256, 256>>>(h2, h3, inv2, KP2, 1024, HC, Xp);
    run_gcn_split(bX2, KP2, 1024, Xp, 1536, Wall + WOFF_U0, HC, bu0, hb, ACT_RELU, 8, 4,
                  xw, t, dis2, zpk);

    k_unpool_pack<<<(2048 * 512 + 255) / 256, 256>>>(h1, hb, inv1, KP1, 2048, HC, Xp);
    run_gcn_exact(bA1, KP1, 2048, Xp, 1536, Wall + WOFF_U1, HC, bu1, hb, ACT_RELU, 4, 2,
                  xw, t, dis1, zpk);

    k_unpool_pack<<<(4096 * 512 + 255) / 256, 256>>>(h0, hb, inv0, N0, 4096, HC, Xp);
    cudaMemsetAsync(xw, 0, (size_t)N0 * 128 * sizeof(float), 0);
    run_nn(N0, 128, 1536, Xp, 1536, Wall + WOFF_U2, 128, xw, 128, 2, 8, nullptr, ACT_NONE);
    k_spmm<<<N0, OC>>>(ccnt, ccol, cval, xw, OC, 128, dis0, bu2, ACT_SIGM, (float*)d_out);
}